// round 12
// baseline (speedup 1.0000x reference)
#include <cuda_runtime.h>

// Problem constants (fixed by setup_inputs)
#define Bn   16
#define D    1024
#define H    16
#define HD   64
#define S    4096
#define SP   4097          // S + 1
#define SPAD 4112          // padded score row stride

// key pass: big-tile cp.async, 8h x 4k register tile, resident qw
#define KCH  512           // key rows per block
#define KNC  9             // ceil(4097/512)
#define KET  32            // e columns per tile (128 B rows -> coalesced)
#define KSTR 36            // smem row stride: conflict-free LDS.128
#define KD   2             // double buffer
#define KNT  (D / KET)     // 32 tiles
#define KSMEM_BYTES ((KD * KCH * KSTR + H * D) * 4)   // 212,992

// value pass (register-direct, R5 WIN — unchanged)
#define VCH  128
#define VNC  33
#define PF   8

// Scratch (device globals; no allocation allowed)
__device__ float g_qw[Bn * H * D];
__device__ float g_scores[Bn * H * SPAD];
__device__ float g_avpart[(size_t)Bn * VNC * H * D];
__device__ float g_ctx[Bn * D];

// ---------------------------------------------------------------------------
// cp.async helpers
// ---------------------------------------------------------------------------
__device__ __forceinline__ void cp16(void* s, const void* g) {
    unsigned a = (unsigned)__cvta_generic_to_shared(s);
    asm volatile("cp.async.cg.shared.global [%0], [%1], 16;" :: "r"(a), "l"(g));
}
__device__ __forceinline__ void cp_commit() { asm volatile("cp.async.commit_group;"); }
template<int N> __device__ __forceinline__ void cp_wait() {
    asm volatile("cp.async.wait_group %0;" :: "n"(N));
}

// ---------------------------------------------------------------------------
// Kernel 1: q projection folded through wk. grid (H, B), 256 threads.
// ---------------------------------------------------------------------------
__global__ void __launch_bounds__(256) k_qproj(const float* __restrict__ query,
                                               const float* __restrict__ w_in,
                                               const float* __restrict__ b_in) {
    __shared__ float qs[D];
    __shared__ float qh[HD];
    const int h = blockIdx.x, b = blockIdx.y, tid = threadIdx.x;

    for (int i = tid; i < D; i += 256) qs[i] = query[b * D + i];
    __syncthreads();

    {
        int d = tid >> 2, sub = tid & 3;
        const float* wrow = w_in + (size_t)(h * HD + d) * D;
        float a = 0.f;
        #pragma unroll 8
        for (int e = sub; e < D; e += 4) a = fmaf(qs[e], wrow[e], a);
        a += __shfl_down_sync(0xffffffffu, a, 2, 4);
        a += __shfl_down_sync(0xffffffffu, a, 1, 4);
        if (sub == 0) qh[d] = (a + b_in[h * HD + d]) * 0.125f;
    }
    __syncthreads();

    for (int e = tid; e < D; e += 256) {
        float a = 0.f;
        #pragma unroll
        for (int d = 0; d < HD; d++)
            a = fmaf(qh[d], w_in[(size_t)(D + h * HD + d) * D + e], a);
        g_qw[(b * H + h) * D + e] = a;
    }
}

// ---------------------------------------------------------------------------
// Kernel 2: key pass — 512-row tiles, double-buffered cp.async, 8h x 4k
// register tile, full qw resident in smem (broadcast LDS, zero conflicts).
//   copies past_key/key -> comb_key AND scores[b,h,k] = key_k · qw[b,h]
// grid (KNC, B), 256 threads, 1 block/SM (213 KB smem).
//   loader lane:  row (tid>>3)+32m, cols (tid&7)*4.. (coalesced 128 B rows)
//   compute lane: hg=(tid>>5)&1 (8 heads), rb=(tid&31)+32*(tid>>6),
//                 rows rb+128*rr — q4 LDS single-address per warp (broadcast),
//                 kv LDS lane-consecutive rows, stride 36 -> conflict-free.
// ---------------------------------------------------------------------------
__global__ void __launch_bounds__(256, 1) k_keys(const float* __restrict__ past_key,
                                                 const float* __restrict__ key,
                                                 float* __restrict__ comb_key) {
    extern __shared__ float sm[];
    float (*ks)[KCH][KSTR] = reinterpret_cast<float (*)[KCH][KSTR]>(sm);
    float* qws = sm + KD * KCH * KSTR;             // [H][D] contiguous

    const int chunk = blockIdx.x, b = blockIdx.y, tid = threadIdx.x;
    const int k0 = chunk * KCH;
    const int lr = tid >> 3;                       // loader row base (0..31)
    const int lc = (tid & 7) * 4;                  // loader col (floats)

    // 16 loop-invariant source row pointers (OOB rows alias current token row)
    const float* rp[16];
    #pragma unroll
    for (int m = 0; m < 16; m++) {
        int kr = k0 + lr + 32 * m;
        rp[m] = ((kr < S) ? past_key + ((size_t)b * S + kr) * D
                          : key + (size_t)b * D) + lc;
    }

    #define KPREF(T, BUF)                                                   \
        do {                                                                \
            const int _et = (T) * KET;                                      \
            _Pragma("unroll")                                               \
            for (int m = 0; m < 16; m++)                                    \
                cp16(&ks[BUF][lr + 32 * m][lc], rp[m] + _et);               \
        } while (0)

    KPREF(0, 0); cp_commit();

    // stage full qw[b] (64 KB) while tile 0 is in flight
    {
        const float4* src = (const float4*)(g_qw + (size_t)b * H * D);
        float4* dst = (float4*)qws;
        for (int i = tid; i < H * D / 4; i += 256) dst[i] = src[i];
    }
    __syncthreads();

    const int hg = (tid >> 5) & 1;                 // head half (8 heads)
    const int rb = (tid & 31) + 32 * (tid >> 6);   // row base (0..127)
    float* dst0 = comb_key + ((size_t)b * SP + k0 + lr) * D + lc;
    const bool full = (chunk < KNC - 1);           // all 512 rows valid

    float acc[8][4];
    #pragma unroll
    for (int a = 0; a < 8; a++)
        #pragma unroll
        for (int r = 0; r < 4; r++) acc[a][r] = 0.f;

    for (int t = 0; t < KNT; t++) {
        cp_wait<KD - 2>();
        __syncthreads();
        if (t + 1 < KNT) KPREF(t + 1, (t + 1) & 1);
        cp_commit();

        const int buf = t & 1;
        const int et = t * KET;

        // copy tile -> comb_key (each thread stores exactly what it loaded)
        #pragma unroll
        for (int m = 0; m < 16; m++) {
            float4 v = *(const float4*)&ks[buf][lr + 32 * m][lc];
            if (full || (k0 + lr + 32 * m) < SP)
                *(float4*)(dst0 + (size_t)32 * m * D + et) = v;
        }
        // scores: 8 heads x 4 rows per thread
        #pragma unroll
        for (int e4 = 0; e4 < KET / 4; e4++) {
            float4 kv[4];
            #pragma unroll
            for (int rr = 0; rr < 4; rr++)
                kv[rr] = *(const float4*)&ks[buf][rb + 128 * rr][e4 * 4];
            #pragma unroll
            for (int hh = 0; hh < 8; hh++) {
                float4 q = *(const float4*)&qws[(8 * hg + hh) * D + et + e4 * 4];
                #pragma unroll
                for (int rr = 0; rr < 4; rr++) {
                    acc[hh][rr] = fmaf(q.x, kv[rr].x, acc[hh][rr]);
                    acc[hh][rr] = fmaf(q.y, kv[rr].y, acc[hh][rr]);
                    acc[hh][rr] = fmaf(q.z, kv[rr].z, acc[hh][rr]);
                    acc[hh][rr] = fmaf(q.w, kv[rr].w, acc[hh][rr]);
                }
            }
        }
    }

    #pragma unroll
    for (int hh = 0; hh < 8; hh++)
        #pragma unroll
        for (int rr = 0; rr < 4; rr++) {
            int k = k0 + rb + 128 * rr;
            if (k < SP)
                g_scores[(size_t)(b * H + 8 * hg + hh) * SPAD + k] = acc[hh][rr];
        }
    #undef KPREF
}

// ---------------------------------------------------------------------------
// Kernel 3: softmax over 4097 scores per (b,h); in place. grid 256, 256 thr.
// ---------------------------------------------------------------------------
__global__ void k_softmax() {
    __shared__ float red[32];
    __shared__ float bc;
    const int tid = threadIdx.x, lane = tid & 31, wid = tid >> 5;
    float* row = g_scores + (size_t)blockIdx.x * SPAD;

    float m = -1e30f;
    for (int i = tid; i < SP; i += 256) m = fmaxf(m, row[i]);
    #pragma unroll
    for (int o = 16; o; o >>= 1) m = fmaxf(m, __shfl_xor_sync(0xffffffffu, m, o));
    if (lane == 0) red[wid] = m;
    __syncthreads();
    if (tid == 0) {
        float v = red[0];
        for (int i = 1; i < 8; i++) v = fmaxf(v, red[i]);
        bc = v;
    }
    __syncthreads();
    const float M = bc;

    float s = 0.f;
    for (int i = tid; i < SP; i += 256) {
        float e = __expf(row[i] - M);
        row[i] = e;
        s += e;
    }
    #pragma unroll
    for (int o = 16; o; o >>= 1) s += __shfl_xor_sync(0xffffffffu, s, o);
    if (lane == 0) red[wid] = s;
    __syncthreads();
    if (tid == 0) {
        float v = 0.f;
        for (int i = 0; i < 8; i++) v += red[i];
        bc = 1.f / v;
    }
    __syncthreads();
    const float inv = bc;
    for (int i = tid; i < SP; i += 256) row[i] *= inv;
}

// ---------------------------------------------------------------------------
// Kernel 4: value pass — register-direct, all 16 heads per thread (R5 WIN,
// unchanged). grid (VNC, B), 256 threads.
// ---------------------------------------------------------------------------
__global__ void __launch_bounds__(256, 2) k_values(const float* __restrict__ past_value,
                                                   const float* __restrict__ value,
                                                   float* __restrict__ comb_value) {
    __shared__ float as[VCH][20];
    const int chunk = blockIdx.x, b = blockIdx.y, tid = threadIdx.x;
    const int k0 = chunk * VCH;

    for (int i = tid; i < VCH * H; i += 256) {
        int h = i >> 7, k = i & (VCH - 1);
        as[k][h] = (k0 + k < SP) ? g_scores[(size_t)(b * H + h) * SPAD + k0 + k] : 0.f;
    }
    __syncthreads();

    const float* vrow_cur = value + (size_t)b * D + tid * 4;
    const float* pv_base  = past_value + ((size_t)b * S) * D + tid * 4;

    float4 acc[16];
    #pragma unroll
    for (int h = 0; h < 16; h++) acc[h] = make_float4(0.f, 0.f, 0.f, 0.f);

    float4 vbuf[PF];
    #pragma unroll
    for (int p = 0; p < PF; p++) {
        int kp = k0 + p;
        vbuf[p] = *(const float4*)((kp < S) ? pv_base + (size_t)kp * D : vrow_cur);
    }

    for (int kb = 0; kb < VCH; kb += PF) {
        #pragma unroll
        for (int p = 0; p < PF; p++) {
            const int k = kb + p;
            const float4 v = vbuf[p];

            if (kb + PF < VCH) {
                int kn = k0 + k + PF;
                vbuf[p] = *(const float4*)((kn < S) ? pv_base + (size_t)kn * D : vrow_cur);
            }
            int kp = k0 + k;
            if (kp < SP)
                *(float4*)(comb_value + ((size_t)b * SP + kp) * D + tid * 4) = v;

            #pragma unroll
            for (int h4 = 0; h4 < 4; h4++) {
                float4 w = *(const float4*)&as[k][h4 * 4];
                acc[h4 * 4 + 0].x = fmaf(w.x, v.x, acc[h4 * 4 + 0].x);
                acc[h4 * 4 + 0].y = fmaf(w.x, v.y, acc[h4 * 4 + 0].y);
                acc[h4 * 4 + 0].z = fmaf(w.x, v.z, acc[h4 * 4 + 0].z);
                acc[h4 * 4 + 0].w = fmaf(w.x, v.w, acc[h4 * 4 + 0].w);
                acc[h4 * 4 + 1].x = fmaf(w.y, v.x, acc[h4 * 4 + 1].x);
                acc[h4 * 4 + 1].y = fmaf(w.y, v.y, acc[h4 * 4 + 1].y);
                acc[h4 * 4 + 1].z = fmaf(w.y, v.z, acc[h4 * 4 + 1].z);
                acc[h4 * 4 + 1].w = fmaf(w.y, v.w, acc[h4 * 4 + 1].w);
                acc[h4 * 4 + 2].x = fmaf(w.z, v.x, acc[h4 * 4 + 2].x);
                acc[h4 * 4 + 2].y = fmaf(w.z, v.y, acc[h4 * 4 + 2].y);
                acc[h4 * 4 + 2].z = fmaf(w.z, v.z, acc[h4 * 4 + 2].z);
                acc[h4 * 4 + 2].w = fmaf(w.z, v.w, acc[h4 * 4 + 2].w);
                acc[h4 * 4 + 3].x = fmaf(w.w, v.x, acc[h4 * 4 + 3].x);
                acc[h4 * 4 + 3].y = fmaf(w.w, v.y, acc[h4 * 4 + 3].y);
                acc[h4 * 4 + 3].z = fmaf(w.w, v.z, acc[h4 * 4 + 3].z);
                acc[h4 * 4 + 3].w = fmaf(w.w, v.w, acc[h4 * 4 + 3].w);
            }
        }
    }

    #pragma unroll
    for (int h = 0; h < 16; h++)
        *(float4*)&g_avpart[(((size_t)b * VNC + chunk) * H + h) * D + tid * 4] = acc[h];
}

// ---------------------------------------------------------------------------
// Kernel 5: fold chunk partials + ctx = av @ wv^T + bv.  grid (H, B), 256 thr.
// ---------------------------------------------------------------------------
__global__ void __launch_bounds__(256) k_fold(const float* __restrict__ w_in,
                                              const float* __restrict__ b_in) {
    __shared__ float avs[D];
    const int h = blockIdx.x, b = blockIdx.y, tid = threadIdx.x;

    for (int e = tid; e < D; e += 256) {
        float s = 0.f;
        #pragma unroll
        for (int c = 0; c < VNC; c++)
            s += g_avpart[(((size_t)b * VNC + c) * H + h) * D + e];
        avs[e] = s;
    }
    __syncthreads();

    int d = tid >> 2, sub = tid & 3;
    const float* wrow = w_in + (size_t)(2 * D + h * HD + d) * D;
    float a = 0.f;
    #pragma unroll 8
    for (int e = sub; e < D; e += 4) a = fmaf(avs[e], wrow[e], a);
    a += __shfl_down_sync(0xffffffffu, a, 2, 4);
    a += __shfl_down_sync(0xffffffffu, a, 1, 4);
    if (sub == 0) g_ctx[b * D + h * HD + d] = a + b_in[2 * D + h * HD + d];
}

// ---------------------------------------------------------------------------
// Kernel 6: out = ctx @ w_out^T + b_out.  grid (16, B), 256 thr.
// ---------------------------------------------------------------------------
__global__ void __launch_bounds__(256) k_out(const float* __restrict__ w_out,
                                             const float* __restrict__ b_out,
                                             float* __restrict__ out) {
    __shared__ float cs[D];
    const int og = blockIdx.x, b = blockIdx.y, tid = threadIdx.x;

    for (int i = tid; i < D; i += 256) cs[i] = g_ctx[b * D + i];
    __syncthreads();

    int o = og * 64 + (tid >> 2), sub = tid & 3;
    const float* wrow = w_out + (size_t)o * D;
    float a = 0.f;
    #pragma unroll 8
    for (int dt = sub; dt < D; dt += 4) a = fmaf(cs[dt], wrow[dt], a);
    a += __shfl_down_sync(0xffffffffu, a, 2, 4);
    a += __shfl_down_sync(0xffffffffu, a, 1, 4);
    if (sub == 0) out[(size_t)b * D + o] = a + b_out[o];
}

// ---------------------------------------------------------------------------
extern "C" void kernel_launch(void* const* d_in, const int* in_sizes, int n_in,
                              void* d_out, int out_size) {
    (void)in_sizes; (void)n_in; (void)out_size;
    const float* query      = (const float*)d_in[0];
    const float* key        = (const float*)d_in[1];
    const float* value      = (const float*)d_in[2];
    const float* past_key   = (const float*)d_in[3];
    const float* past_value = (const float*)d_in[4];
    const float* w_in       = (const float*)d_in[5];
    const float* b_in       = (const float*)d_in[6];
    const float* w_out      = (const float*)d_in[7];
    const float* b_out      = (const float*)d_in[8];

    float* out        = (float*)d_out;                      // [16,1,1024]
    float* comb_key   = out + (size_t)Bn * D;               // [16,4097,1024]
    float* comb_value = comb_key + (size_t)Bn * SP * D;     // [16,4097,1024]

    cudaFuncSetAttribute(k_keys, cudaFuncAttributeMaxDynamicSharedMemorySize, KSMEM_BYTES);

    k_qproj  <<<dim3(H, Bn),   256>>>(query, w_in, b_in);
    k_keys   <<<dim3(KNC, Bn), 256, KSMEM_BYTES>>>(past_key, key, comb_key);
    k_softmax<<<Bn * H,        256>>>();
    k_values <<<dim3(VNC, Bn), 256>>>(past_value, value, comb_value);
    k_fold   <<<dim3(H, Bn),   256>>>(w_in, b_in);
    k_out    <<<dim3(16, Bn),  256>>>(w_out, b_out, out);
}

// round 13
// speedup vs baseline: 1.0312x; 1.0312x over previous
#include <cuda_runtime.h>

// Problem constants (fixed by setup_inputs)
#define Bn   16
#define D    1024
#define H    16
#define HD   64
#define S    4096
#define SP   4097          // S + 1
#define SPAD 4112          // padded score row stride

// key pass: KD=2 cp.async, resident qw, 2 blocks/SM
#define KCH  128           // key rows per block
#define KNC  33            // ceil(4097/128)
#define KET  32            // e columns per tile
#define KSTR 36            // smem row stride: conflict-free LDS.128
#define KD   2             // double buffer
#define KNT  (D / KET)     // 32 tiles
#define KSMEM_BYTES ((KD * KCH * KSTR + H * D) * 4)   // 102,400 -> 2 blocks/SM

// value pass (register-direct, R5 WIN — unchanged)
#define VCH  128
#define VNC  33
#define PF   8

// Scratch (device globals; no allocation allowed)
__device__ float g_qw[Bn * H * D];
__device__ float g_scores[Bn * H * SPAD];
__device__ float g_avpart[(size_t)Bn * VNC * H * D];
__device__ float g_ctx[Bn * D];

// ---------------------------------------------------------------------------
// cp.async helpers
// ---------------------------------------------------------------------------
__device__ __forceinline__ void cp16(void* s, const void* g) {
    unsigned a = (unsigned)__cvta_generic_to_shared(s);
    asm volatile("cp.async.cg.shared.global [%0], [%1], 16;" :: "r"(a), "l"(g));
}
__device__ __forceinline__ void cp_commit() { asm volatile("cp.async.commit_group;"); }
template<int N> __device__ __forceinline__ void cp_wait() {
    asm volatile("cp.async.wait_group %0;" :: "n"(N));
}

// ---------------------------------------------------------------------------
// Kernel 1: q projection folded through wk. grid (H, B), 256 threads.
// ---------------------------------------------------------------------------
__global__ void __launch_bounds__(256) k_qproj(const float* __restrict__ query,
                                               const float* __restrict__ w_in,
                                               const float* __restrict__ b_in) {
    __shared__ float qs[D];
    __shared__ float qh[HD];
    const int h = blockIdx.x, b = blockIdx.y, tid = threadIdx.x;

    for (int i = tid; i < D; i += 256) qs[i] = query[b * D + i];
    __syncthreads();

    {
        int d = tid >> 2, sub = tid & 3;
        const float* wrow = w_in + (size_t)(h * HD + d) * D;
        float a = 0.f;
        #pragma unroll 8
        for (int e = sub; e < D; e += 4) a = fmaf(qs[e], wrow[e], a);
        a += __shfl_down_sync(0xffffffffu, a, 2, 4);
        a += __shfl_down_sync(0xffffffffu, a, 1, 4);
        if (sub == 0) qh[d] = (a + b_in[h * HD + d]) * 0.125f;
    }
    __syncthreads();

    for (int e = tid; e < D; e += 256) {
        float a = 0.f;
        #pragma unroll
        for (int d = 0; d < HD; d++)
            a = fmaf(qh[d], w_in[(size_t)(D + h * HD + d) * D + e], a);
        g_qw[(b * H + h) * D + e] = a;
    }
}

// ---------------------------------------------------------------------------
// Kernel 2: key pass — KD=2 cp.async tiles + full qw resident in smem.
//   copies past_key/key -> comb_key AND scores[b,h,k] = key_k · qw[b,h]
// grid (KNC, B), 256 threads, 2 blocks/SM (100 KB smem).
//   loader: row (tid>>3)+32m, col (tid&7)*4 — 4-line coalesced.
//   compute: warp w: head-quad w&3, row half w>>2; rows lane+64*(w>>2)+{0,32}.
//   qw LDS warp-uniform (broadcast); kv LDS stride-36 conflict-free.
// ---------------------------------------------------------------------------
__global__ void __launch_bounds__(256, 2) k_keys(const float* __restrict__ past_key,
                                                 const float* __restrict__ key,
                                                 float* __restrict__ comb_key) {
    extern __shared__ float sm[];
    float (*ks)[KCH][KSTR] = reinterpret_cast<float (*)[KCH][KSTR]>(sm);
    float* qws = sm + KD * KCH * KSTR;             // [H][D] contiguous, resident

    const int chunk = blockIdx.x, b = blockIdx.y, tid = threadIdx.x;
    const int k0 = chunk * KCH;
    const int w = tid >> 5, lane = tid & 31;
    const int hq = w & 3, kh = w >> 2;
    const int lr = tid >> 3;                       // loader row base (0..31)
    const int lc = (tid & 7) * 4;                  // loader col (floats)

    // loop-invariant source pointers (OOB rows alias current-token row)
    const float* rp[4];
    #pragma unroll
    for (int m = 0; m < 4; m++) {
        int kr = k0 + lr + 32 * m;
        rp[m] = ((kr < S) ? past_key + ((size_t)b * S + kr) * D
                          : key + (size_t)b * D) + lc;
    }

    #define KPREF(T, BUF)                                                   \
        do {                                                                \
            const int _et = (T) * KET;                                      \
            _Pragma("unroll")                                               \
            for (int m = 0; m < 4; m++)                                     \
                cp16(&ks[BUF][lr + 32 * m][lc], rp[m] + _et);               \
        } while (0)

    KPREF(0, 0); cp_commit();

    // stage full qw[b] (64 KB) once, while tile 0 is in flight
    {
        const float4* src = (const float4*)(g_qw + (size_t)b * H * D);
        float4* dst = (float4*)qws;
        for (int i = tid; i < H * D / 4; i += 256) dst[i] = src[i];
    }

    const int r0 = lane + 64 * kh;                 // rows r0, r0+32
    float* dst0 = comb_key + ((size_t)b * SP + k0 + lr) * D + lc;

    float acc[4][2];
    #pragma unroll
    for (int a = 0; a < 4; a++) { acc[a][0] = 0.f; acc[a][1] = 0.f; }

    for (int t = 0; t < KNT; t++) {
        cp_wait<0>();                              // tile t arrived
        __syncthreads();                           // + prev compute done, qw visible
        if (t + 1 < KNT) { KPREF(t + 1, (t + 1) & 1); cp_commit(); }

        const int buf = t & 1;
        const int et = t * KET;

        // copy tile -> comb_key
        #pragma unroll
        for (int m = 0; m < 4; m++) {
            float4 v = *(const float4*)&ks[buf][lr + 32 * m][lc];
            if (k0 + lr + 32 * m < SP)
                *(float4*)(dst0 + (size_t)32 * m * D + et) = v;
        }
        // scores: 4 heads x 2 rows per thread
        const float* qb = qws + (4 * hq) * D + et;
        #pragma unroll
        for (int e4 = 0; e4 < KET / 4; e4++) {
            float4 kv0 = *(const float4*)&ks[buf][r0][e4 * 4];
            float4 kv1 = *(const float4*)&ks[buf][r0 + 32][e4 * 4];
            #pragma unroll
            for (int hh = 0; hh < 4; hh++) {
                float4 q4 = *(const float4*)(qb + hh * D + e4 * 4);
                acc[hh][0] = fmaf(q4.x, kv0.x, acc[hh][0]);
                acc[hh][0] = fmaf(q4.y, kv0.y, acc[hh][0]);
                acc[hh][0] = fmaf(q4.z, kv0.z, acc[hh][0]);
                acc[hh][0] = fmaf(q4.w, kv0.w, acc[hh][0]);
                acc[hh][1] = fmaf(q4.x, kv1.x, acc[hh][1]);
                acc[hh][1] = fmaf(q4.y, kv1.y, acc[hh][1]);
                acc[hh][1] = fmaf(q4.z, kv1.z, acc[hh][1]);
                acc[hh][1] = fmaf(q4.w, kv1.w, acc[hh][1]);
            }
        }
        __syncthreads();                           // protect buf before next PREF
    }

    #pragma unroll
    for (int hh = 0; hh < 4; hh++)
        #pragma unroll
        for (int jj = 0; jj < 2; jj++) {
            int k = k0 + r0 + 32 * jj;
            if (k < SP)
                g_scores[(size_t)(b * H + 4 * hq + hh) * SPAD + k] = acc[hh][jj];
        }
    #undef KPREF
}

// ---------------------------------------------------------------------------
// Kernel 3: softmax over 4097 scores per (b,h); in place. grid 256, 256 thr.
// ---------------------------------------------------------------------------
__global__ void k_softmax() {
    __shared__ float red[32];
    __shared__ float bc;
    const int tid = threadIdx.x, lane = tid & 31, wid = tid >> 5;
    float* row = g_scores + (size_t)blockIdx.x * SPAD;

    float m = -1e30f;
    for (int i = tid; i < SP; i += 256) m = fmaxf(m, row[i]);
    #pragma unroll
    for (int o = 16; o; o >>= 1) m = fmaxf(m, __shfl_xor_sync(0xffffffffu, m, o));
    if (lane == 0) red[wid] = m;
    __syncthreads();
    if (tid == 0) {
        float v = red[0];
        for (int i = 1; i < 8; i++) v = fmaxf(v, red[i]);
        bc = v;
    }
    __syncthreads();
    const float M = bc;

    float s = 0.f;
    for (int i = tid; i < SP; i += 256) {
        float e = __expf(row[i] - M);
        row[i] = e;
        s += e;
    }
    #pragma unroll
    for (int o = 16; o; o >>= 1) s += __shfl_xor_sync(0xffffffffu, s, o);
    if (lane == 0) red[wid] = s;
    __syncthreads();
    if (tid == 0) {
        float v = 0.f;
        for (int i = 0; i < 8; i++) v += red[i];
        bc = 1.f / v;
    }
    __syncthreads();
    const float inv = bc;
    for (int i = tid; i < SP; i += 256) row[i] *= inv;
}

// ---------------------------------------------------------------------------
// Kernel 4: value pass — register-direct, all 16 heads per thread (R5 WIN,
// unchanged). grid (VNC, B), 256 threads.
// ---------------------------------------------------------------------------
__global__ void __launch_bounds__(256, 2) k_values(const float* __restrict__ past_value,
                                                   const float* __restrict__ value,
                                                   float* __restrict__ comb_value) {
    __shared__ float as[VCH][20];
    const int chunk = blockIdx.x, b = blockIdx.y, tid = threadIdx.x;
    const int k0 = chunk * VCH;

    for (int i = tid; i < VCH * H; i += 256) {
        int h = i >> 7, k = i & (VCH - 1);
        as[k][h] = (k0 + k < SP) ? g_scores[(size_t)(b * H + h) * SPAD + k0 + k] : 0.f;
    }
    __syncthreads();

    const float* vrow_cur = value + (size_t)b * D + tid * 4;
    const float* pv_base  = past_value + ((size_t)b * S) * D + tid * 4;

    float4 acc[16];
    #pragma unroll
    for (int h = 0; h < 16; h++) acc[h] = make_float4(0.f, 0.f, 0.f, 0.f);

    float4 vbuf[PF];
    #pragma unroll
    for (int p = 0; p < PF; p++) {
        int kp = k0 + p;
        vbuf[p] = *(const float4*)((kp < S) ? pv_base + (size_t)kp * D : vrow_cur);
    }

    for (int kb = 0; kb < VCH; kb += PF) {
        #pragma unroll
        for (int p = 0; p < PF; p++) {
            const int k = kb + p;
            const float4 v = vbuf[p];

            if (kb + PF < VCH) {
                int kn = k0 + k + PF;
                vbuf[p] = *(const float4*)((kn < S) ? pv_base + (size_t)kn * D : vrow_cur);
            }
            int kp = k0 + k;
            if (kp < SP)
                *(float4*)(comb_value + ((size_t)b * SP + kp) * D + tid * 4) = v;

            #pragma unroll
            for (int h4 = 0; h4 < 4; h4++) {
                float4 w = *(const float4*)&as[k][h4 * 4];
                acc[h4 * 4 + 0].x = fmaf(w.x, v.x, acc[h4 * 4 + 0].x);
                acc[h4 * 4 + 0].y = fmaf(w.x, v.y, acc[h4 * 4 + 0].y);
                acc[h4 * 4 + 0].z = fmaf(w.x, v.z, acc[h4 * 4 + 0].z);
                acc[h4 * 4 + 0].w = fmaf(w.x, v.w, acc[h4 * 4 + 0].w);
                acc[h4 * 4 + 1].x = fmaf(w.y, v.x, acc[h4 * 4 + 1].x);
                acc[h4 * 4 + 1].y = fmaf(w.y, v.y, acc[h4 * 4 + 1].y);
                acc[h4 * 4 + 1].z = fmaf(w.y, v.z, acc[h4 * 4 + 1].z);
                acc[h4 * 4 + 1].w = fmaf(w.y, v.w, acc[h4 * 4 + 1].w);
                acc[h4 * 4 + 2].x = fmaf(w.z, v.x, acc[h4 * 4 + 2].x);
                acc[h4 * 4 + 2].y = fmaf(w.z, v.y, acc[h4 * 4 + 2].y);
                acc[h4 * 4 + 2].z = fmaf(w.z, v.z, acc[h4 * 4 + 2].z);
                acc[h4 * 4 + 2].w = fmaf(w.z, v.w, acc[h4 * 4 + 2].w);
                acc[h4 * 4 + 3].x = fmaf(w.w, v.x, acc[h4 * 4 + 3].x);
                acc[h4 * 4 + 3].y = fmaf(w.w, v.y, acc[h4 * 4 + 3].y);
                acc[h4 * 4 + 3].z = fmaf(w.w, v.z, acc[h4 * 4 + 3].z);
                acc[h4 * 4 + 3].w = fmaf(w.w, v.w, acc[h4 * 4 + 3].w);
            }
        }
    }

    #pragma unroll
    for (int h = 0; h < 16; h++)
        *(float4*)&g_avpart[(((size_t)b * VNC + chunk) * H + h) * D + tid * 4] = acc[h];
}

// ---------------------------------------------------------------------------
// Kernel 5: fold chunk partials + ctx = av @ wv^T + bv.  grid (H, B), 256 thr.
// ---------------------------------------------------------------------------
__global__ void __launch_bounds__(256) k_fold(const float* __restrict__ w_in,
                                              const float* __restrict__ b_in) {
    __shared__ float avs[D];
    const int h = blockIdx.x, b = blockIdx.y, tid = threadIdx.x;

    for (int e = tid; e < D; e += 256) {
        float s = 0.f;
        #pragma unroll
        for (int c = 0; c < VNC; c++)
            s += g_avpart[(((size_t)b * VNC + c) * H + h) * D + e];
        avs[e] = s;
    }
    __syncthreads();

    int d = tid >> 2, sub = tid & 3;
    const float* wrow = w_in + (size_t)(2 * D + h * HD + d) * D;
    float a = 0.f;
    #pragma unroll 8
    for (int e = sub; e < D; e += 4) a = fmaf(avs[e], wrow[e], a);
    a += __shfl_down_sync(0xffffffffu, a, 2, 4);
    a += __shfl_down_sync(0xffffffffu, a, 1, 4);
    if (sub == 0) g_ctx[b * D + h * HD + d] = a + b_in[2 * D + h * HD + d];
}

// ---------------------------------------------------------------------------
// Kernel 6: out = ctx @ w_out^T + b_out.  grid (16, B), 256 thr.
// ---------------------------------------------------------------------------
__global__ void __launch_bounds__(256) k_out(const float* __restrict__ w_out,
                                             const float* __restrict__ b_out,
                                             float* __restrict__ out) {
    __shared__ float cs[D];
    const int og = blockIdx.x, b = blockIdx.y, tid = threadIdx.x;

    for (int i = tid; i < D; i += 256) cs[i] = g_ctx[b * D + i];
    __syncthreads();

    int o = og * 64 + (tid >> 2), sub = tid & 3;
    const float* wrow = w_out + (size_t)o * D;
    float a = 0.f;
    #pragma unroll 8
    for (int dt = sub; dt < D; dt += 4) a = fmaf(cs[dt], wrow[dt], a);
    a += __shfl_down_sync(0xffffffffu, a, 2, 4);
    a += __shfl_down_sync(0xffffffffu, a, 1, 4);
    if (sub == 0) out[(size_t)b * D + o] = a + b_out[o];
}

// ---------------------------------------------------------------------------
extern "C" void kernel_launch(void* const* d_in, const int* in_sizes, int n_in,
                              void* d_out, int out_size) {
    (void)in_sizes; (void)n_in; (void)out_size;
    const float* query      = (const float*)d_in[0];
    const float* key        = (const float*)d_in[1];
    const float* value      = (const float*)d_in[2];
    const float* past_key   = (const float*)d_in[3];
    const float* past_value = (const float*)d_in[4];
    const float* w_in       = (const float*)d_in[5];
    const float* b_in       = (const float*)d_in[6];
    const float* w_out      = (const float*)d_in[7];
    const float* b_out      = (const float*)d_in[8];

    float* out        = (float*)d_out;                      // [16,1,1024]
    float* comb_key   = out + (size_t)Bn * D;               // [16,4097,1024]
    float* comb_value = comb_key + (size_t)Bn * SP * D;     // [16,4097,1024]

    cudaFuncSetAttribute(k_keys, cudaFuncAttributeMaxDynamicSharedMemorySize, KSMEM_BYTES);

    k_qproj  <<<dim3(H, Bn),   256>>>(query, w_in, b_in);
    k_keys   <<<dim3(KNC, Bn), 256, KSMEM_BYTES>>>(past_key, key, comb_key);
    k_softmax<<<Bn * H,        256>>>();
    k_values <<<dim3(VNC, Bn), 256>>>(past_value, value, comb_value);
    k_fold   <<<dim3(H, Bn),   256>>>(w_in, b_in);
    k_out    <<<dim3(16, Bn),  256>>>(w_out, b_out, out);
}

// round 16
// speedup vs baseline: 1.2539x; 1.2159x over previous
#include <cuda_runtime.h>

// Problem constants (fixed by setup_inputs)
#define Bn   16
#define D    1024
#define H    16
#define HD   64
#define S    4096
#define SP   4097          // S + 1

// fused streaming kernel tiling
#define KCH  128           // kv rows per block/chunk
#define NC   33            // ceil(4097/128)
#define KET  32            // e columns per cp.async tile (K phase)
#define KSTR 36            // smem row stride: conflict-free LDS.128
#define KD   3             // K-phase pipeline depth
#define KNT  (D / KET)     // 32 tiles
#define PF   8             // V-phase rolling register prefetch depth

#define SM_KS   (KD * KCH * KSTR)      // 13824 floats
#define SM_QWS  (KD * H * KET)         // 1536 floats
#define SM_AS   (KCH * 20)             // 2560 floats (attn weights [k][h])
#define SMEM_BYTES ((SM_KS + SM_QWS + SM_AS) * 4)   // 71680 B -> 2 blocks/SM

// Scratch (device globals; no allocation allowed)
__device__ float g_qw[Bn * H * D];                    // folded query (q @ wk^T)
__device__ float g_avpart[(size_t)Bn * NC * H * D];   // unnormalized chunk partials
__device__ float g_ms[Bn * NC * H];                   // per-chunk local max
__device__ float g_ss[Bn * NC * H];                   // per-chunk local expsum
__device__ float g_ctx[Bn * D];                       // context after fold

// ---------------------------------------------------------------------------
// cp.async helpers
// ---------------------------------------------------------------------------
__device__ __forceinline__ void cp16(void* s, const void* g) {
    unsigned a = (unsigned)__cvta_generic_to_shared(s);
    asm volatile("cp.async.cg.shared.global [%0], [%1], 16;" :: "r"(a), "l"(g));
}
__device__ __forceinline__ void cp_commit() { asm volatile("cp.async.commit_group;"); }
template<int N> __device__ __forceinline__ void cp_wait() {
    asm volatile("cp.async.wait_group %0;" :: "n"(N));
}

// ---------------------------------------------------------------------------
// Kernel 1: q projection folded through wk. grid (H, B), 256 threads.
// ---------------------------------------------------------------------------
__global__ void __launch_bounds__(256) k_qproj(const float* __restrict__ query,
                                               const float* __restrict__ w_in,
                                               const float* __restrict__ b_in) {
    __shared__ float qs[D];
    __shared__ float qh[HD];
    const int h = blockIdx.x, b = blockIdx.y, tid = threadIdx.x;

    for (int i = tid; i < D; i += 256) qs[i] = query[b * D + i];
    __syncthreads();

    {
        int d = tid >> 2, sub = tid & 3;
        const float* wrow = w_in + (size_t)(h * HD + d) * D;
        float a = 0.f;
        #pragma unroll 8
        for (int e = sub; e < D; e += 4) a = fmaf(qs[e], wrow[e], a);
        a += __shfl_down_sync(0xffffffffu, a, 2, 4);
        a += __shfl_down_sync(0xffffffffu, a, 1, 4);
        if (sub == 0) qh[d] = (a + b_in[h * HD + d]) * 0.125f;
    }
    __syncthreads();

    for (int e = tid; e < D; e += 256) {
        float a = 0.f;
        #pragma unroll
        for (int d = 0; d < HD; d++)
            a = fmaf(qh[d], w_in[(size_t)(D + h * HD + d) * D + e], a);
        g_qw[(b * H + h) * D + e] = a;
    }
}

// ---------------------------------------------------------------------------
// Kernel 2: fused streaming pass (split-KV flash decode).
//   Phase K (R5-proven): cp.async KD=3 pipeline; copies keys -> comb_key,
//     scores -> smem as[k][h] (-1e30 for OOB rows).
//   Local softmax: per-head max / exp / sum over the chunk's 128 rows.
//   Phase V (R5-proven register-direct): copies values -> comb_value,
//     accumulates UNNORMALIZED partials; writes (M_c, S_c) for the fold.
// grid (NC, B), 256 threads, 2 blocks/SM.
// ---------------------------------------------------------------------------
__global__ void __launch_bounds__(256, 2) k_stream(const float* __restrict__ past_key,
                                                   const float* __restrict__ key,
                                                   const float* __restrict__ past_value,
                                                   const float* __restrict__ value,
                                                   float* __restrict__ comb_key,
                                                   float* __restrict__ comb_value) {
    extern __shared__ float sm[];
    float (*ks)[KCH][KSTR] = reinterpret_cast<float (*)[KCH][KSTR]>(sm);
    float (*qws)[H][KET]   = reinterpret_cast<float (*)[H][KET]>(sm + SM_KS);
    float (*as)[20]        = reinterpret_cast<float (*)[20]>(sm + SM_KS + SM_QWS);
    __shared__ float red[H][17];
    __shared__ float bcM[H];

    const int chunk = blockIdx.x, b = blockIdx.y, tid = threadIdx.x;
    const int k0 = chunk * KCH;

    // ============================ K PHASE ============================
    {
        const int w = tid >> 5, lane = tid & 31;
        const int hq = w & 3, kh = w >> 2;
        const int pr = tid >> 3, pc = (tid & 7) * 4;

        const float* srcs[4];
        #pragma unroll
        for (int m = 0; m < 4; m++) {
            int kp = k0 + pr + 32 * m;
            srcs[m] = (kp < S) ? past_key + ((size_t)b * S + kp) * D + pc
                               : key + (size_t)b * D + pc;
        }
        const float* qsrc = g_qw + ((size_t)(b * H) + (tid >> 3)) * D + pc;

        #define KPREFETCH(T, BUF)                                           \
            do {                                                            \
                const int _et = (T) * KET;                                  \
                _Pragma("unroll")                                           \
                for (int m = 0; m < 4; m++)                                 \
                    cp16(&ks[BUF][pr + 32 * m][pc], srcs[m] + _et);         \
                if (tid < 128) cp16(&qws[BUF][tid >> 3][pc], qsrc + _et);   \
            } while (0)

        KPREFETCH(0, 0); cp_commit();
        KPREFETCH(1, 1); cp_commit();

        float acc[4][2];
        #pragma unroll
        for (int a = 0; a < 4; a++) { acc[a][0] = 0.f; acc[a][1] = 0.f; }

        const int r0 = lane + 64 * kh;

        for (int t = 0; t < KNT; t++) {
            cp_wait<KD - 2>();
            __syncthreads();
            if (t + KD - 1 < KNT) KPREFETCH(t + KD - 1, (t + KD - 1) % KD);
            cp_commit();

            const int buf = t % KD;
            const int et = t * KET;

            #pragma unroll
            for (int m = 0; m < 4; m++) {
                int kp = k0 + pr + 32 * m;
                if (kp < SP)
                    *(float4*)(comb_key + ((size_t)b * SP + kp) * D + et + pc)
                        = *(const float4*)&ks[buf][pr + 32 * m][pc];
            }
            #pragma unroll
            for (int e4 = 0; e4 < KET / 4; e4++) {
                float4 kv0 = *(const float4*)&ks[buf][r0][e4 * 4];
                float4 kv1 = *(const float4*)&ks[buf][r0 + 32][e4 * 4];
                #pragma unroll
                for (int hh = 0; hh < 4; hh++) {
                    float4 q4 = *(const float4*)&qws[buf][4 * hq + hh][e4 * 4];
                    acc[hh][0] = fmaf(q4.x, kv0.x, acc[hh][0]);
                    acc[hh][0] = fmaf(q4.y, kv0.y, acc[hh][0]);
                    acc[hh][0] = fmaf(q4.z, kv0.z, acc[hh][0]);
                    acc[hh][0] = fmaf(q4.w, kv0.w, acc[hh][0]);
                    acc[hh][1] = fmaf(q4.x, kv1.x, acc[hh][1]);
                    acc[hh][1] = fmaf(q4.y, kv1.y, acc[hh][1]);
                    acc[hh][1] = fmaf(q4.z, kv1.z, acc[hh][1]);
                    acc[hh][1] = fmaf(q4.w, kv1.w, acc[hh][1]);
                }
            }
        }
        #undef KPREFETCH

        // scores -> smem; OOB rows get -1e30 (-> weight 0 after exp)
        __syncthreads();
        #pragma unroll
        for (int hh = 0; hh < 4; hh++)
            #pragma unroll
            for (int jj = 0; jj < 2; jj++) {
                int r = r0 + 32 * jj;
                as[r][4 * hq + hh] = (k0 + r < SP) ? acc[hh][jj] : -1e30f;
            }
    }
    __syncthreads();

    // ======================== LOCAL SOFTMAX ==========================
    {
        const int h = tid & 15, seg = tid >> 4;
        float mloc = -1e30f;
        #pragma unroll
        for (int i = 0; i < 8; i++) mloc = fmaxf(mloc, as[seg * 8 + i][h]);
        red[h][seg] = mloc;
        __syncthreads();
        if (tid < H) {
            float m = red[tid][0];
            #pragma unroll
            for (int s2 = 1; s2 < 16; s2++) m = fmaxf(m, red[tid][s2]);
            bcM[tid] = m;
        }
        __syncthreads();
        const float M = bcM[h];
        float sloc = 0.f;
        #pragma unroll
        for (int i = 0; i < 8; i++) {
            float e = __expf(as[seg * 8 + i][h] - M);
            as[seg * 8 + i][h] = e;
            sloc += e;
        }
        red[h][seg] = sloc;
        __syncthreads();
        if (tid < H) {
            float s2 = 0.f;
            #pragma unroll
            for (int q = 0; q < 16; q++) s2 += red[tid][q];
            g_ms[(b * NC + chunk) * H + tid] = bcM[tid];
            g_ss[(b * NC + chunk) * H + tid] = s2;
        }
    }
    __syncthreads();

    // ============================ V PHASE ============================
    {
        const float* vrow_cur = value + (size_t)b * D + tid * 4;
        const float* pv_base  = past_value + ((size_t)b * S) * D + tid * 4;

        float4 acc[16];
        #pragma unroll
        for (int h = 0; h < 16; h++) acc[h] = make_float4(0.f, 0.f, 0.f, 0.f);

        float4 vbuf[PF];
        #pragma unroll
        for (int p = 0; p < PF; p++) {
            int kp = k0 + p;
            vbuf[p] = *(const float4*)((kp < S) ? pv_base + (size_t)kp * D : vrow_cur);
        }

        for (int kb = 0; kb < KCH; kb += PF) {
            #pragma unroll
            for (int p = 0; p < PF; p++) {
                const int k = kb + p;
                const float4 v = vbuf[p];

                if (kb + PF < KCH) {
                    int kn = k0 + k + PF;
                    vbuf[p] = *(const float4*)((kn < S) ? pv_base + (size_t)kn * D : vrow_cur);
                }
                int kp = k0 + k;
                if (kp < SP)
                    *(float4*)(comb_value + ((size_t)b * SP + kp) * D + tid * 4) = v;

                #pragma unroll
                for (int h4 = 0; h4 < 4; h4++) {
                    float4 w = *(const float4*)&as[k][h4 * 4];
                    acc[h4 * 4 + 0].x = fmaf(w.x, v.x, acc[h4 * 4 + 0].x);
                    acc[h4 * 4 + 0].y = fmaf(w.x, v.y, acc[h4 * 4 + 0].y);
                    acc[h4 * 4 + 0].z = fmaf(w.x, v.z, acc[h4 * 4 + 0].z);
                    acc[h4 * 4 + 0].w = fmaf(w.x, v.w, acc[h4 * 4 + 0].w);
                    acc[h4 * 4 + 1].x = fmaf(w.y, v.x, acc[h4 * 4 + 1].x);
                    acc[h4 * 4 + 1].y = fmaf(w.y, v.y, acc[h4 * 4 + 1].y);
                    acc[h4 * 4 + 1].z = fmaf(w.y, v.z, acc[h4 * 4 + 1].z);
                    acc[h4 * 4 + 1].w = fmaf(w.y, v.w, acc[h4 * 4 + 1].w);
                    acc[h4 * 4 + 2].x = fmaf(w.z, v.x, acc[h4 * 4 + 2].x);
                    acc[h4 * 4 + 2].y = fmaf(w.z, v.y, acc[h4 * 4 + 2].y);
                    acc[h4 * 4 + 2].z = fmaf(w.z, v.z, acc[h4 * 4 + 2].z);
                    acc[h4 * 4 + 2].w = fmaf(w.z, v.w, acc[h4 * 4 + 2].w);
                    acc[h4 * 4 + 3].x = fmaf(w.w, v.x, acc[h4 * 4 + 3].x);
                    acc[h4 * 4 + 3].y = fmaf(w.w, v.y, acc[h4 * 4 + 3].y);
                    acc[h4 * 4 + 3].z = fmaf(w.w, v.z, acc[h4 * 4 + 3].z);
                    acc[h4 * 4 + 3].w = fmaf(w.w, v.w, acc[h4 * 4 + 3].w);
                }
            }
        }

        #pragma unroll
        for (int h = 0; h < 16; h++)
            *(float4*)&g_avpart[(((size_t)b * NC + chunk) * H + h) * D + tid * 4] = acc[h];
    }
}

// ---------------------------------------------------------------------------
// Kernel 3: fold chunk partials with flash rescaling + ctx = av @ wv^T + bv.
// grid (H, B), 256 threads.
// ---------------------------------------------------------------------------
__global__ void __launch_bounds__(256) k_fold(const float* __restrict__ w_in,
                                              const float* __restrict__ b_in) {
    __shared__ float avs[D];
    __shared__ float wch[NC];
    __shared__ float sinv;
    const int h = blockIdx.x, b = blockIdx.y, tid = threadIdx.x;

    if (tid == 0) {
        float M = -1e30f;
        for (int c = 0; c < NC; c++)
            M = fmaxf(M, g_ms[(b * NC + c) * H + h]);
        float Ssum = 0.f;
        for (int c = 0; c < NC; c++) {
            float w = __expf(g_ms[(b * NC + c) * H + h] - M);
            wch[c] = w;
            Ssum += w * g_ss[(b * NC + c) * H + h];
        }
        sinv = 1.f / Ssum;
    }
    __syncthreads();

    for (int e = tid; e < D; e += 256) {
        float s = 0.f;
        #pragma unroll
        for (int c = 0; c < NC; c++)
            s += g_avpart[(((size_t)b * NC + c) * H + h) * D + e] * wch[c];
        avs[e] = s;
    }
    __syncthreads();

    int d = tid >> 2, sub = tid & 3;
    const float* wrow = w_in + (size_t)(2 * D + h * HD + d) * D;
    float a = 0.f;
    #pragma unroll 8
    for (int e = sub; e < D; e += 4) a = fmaf(avs[e], wrow[e], a);
    a += __shfl_down_sync(0xffffffffu, a, 2, 4);
    a += __shfl_down_sync(0xffffffffu, a, 1, 4);
    if (sub == 0) g_ctx[b * D + h * HD + d] = a * sinv + b_in[2 * D + h * HD + d];
}

// ---------------------------------------------------------------------------
// Kernel 4: out = ctx @ w_out^T + b_out.  grid (16, B), 256 thr.
// ---------------------------------------------------------------------------
__global__ void __launch_bounds__(256) k_out(const float* __restrict__ w_out,
                                             const float* __restrict__ b_out,
                                             float* __restrict__ out) {
    __shared__ float cs[D];
    const int og = blockIdx.x, b = blockIdx.y, tid = threadIdx.x;

    for (int i = tid; i < D; i += 256) cs[i] = g_ctx[b * D + i];
    __syncthreads();

    int o = og * 64 + (tid >> 2), sub = tid & 3;
    const float* wrow = w_out + (size_t)o * D;
    float a = 0.f;
    #pragma unroll 8
    for (int dt = sub; dt < D; dt += 4) a = fmaf(cs[dt], wrow[dt], a);
    a += __shfl_down_sync(0xffffffffu, a, 2, 4);
    a += __shfl_down_sync(0xffffffffu, a, 1, 4);
    if (sub == 0) out[(size_t)b * D + o] = a + b_out[o];
}

// ---------------------------------------------------------------------------
extern "C" void kernel_launch(void* const* d_in, const int* in_sizes, int n_in,
                              void* d_out, int out_size) {
    (void)in_sizes; (void)n_in; (void)out_size;
    const float* query      = (const float*)d_in[0];
    const float* key        = (const float*)d_in[1];
    const float* value      = (const float*)d_in[2];
    const float* past_key   = (const float*)d_in[3];
    const float* past_value = (const float*)d_in[4];
    const float* w_in       = (const float*)d_in[5];
    const float* b_in       = (const float*)d_in[6];
    const float* w_out      = (const float*)d_in[7];
    const float* b_out      = (const float*)d_in[8];

    float* out        = (float*)d_out;                      // [16,1,1024]
    float* comb_key   = out + (size_t)Bn * D;               // [16,4097,1024]
    float* comb_value = comb_key + (size_t)Bn * SP * D;     // [16,4097,1024]

    cudaFuncSetAttribute(k_stream, cudaFuncAttributeMaxDynamicSharedMemorySize, SMEM_BYTES);

    k_qproj <<<dim3(H, Bn),  256>>>(query, w_in, b_in);
    k_stream<<<dim3(NC, Bn), 256, SMEM_BYTES>>>(past_key, key, past_value, value,
                                                comb_key, comb_value);
    k_fold  <<<dim3(H, Bn),  256>>>(w_in, b_in);
    k_out   <<<dim3(16, Bn), 256>>>(w_out, b_out, out);
}

// round 17
// speedup vs baseline: 1.2725x; 1.0148x over previous
#include <cuda_runtime.h>

// Problem constants (fixed by setup_inputs)
#define Bn   16
#define D    1024
#define H    16
#define HD   64
#define S    4096
#define SP   4097          // S + 1

// fused streaming kernel tiling
#define KCH  128           // kv rows per block/chunk
#define NC   33            // ceil(4097/128)
#define KET  32            // e columns per cp.async tile (K phase)
#define KSTR 36            // smem row stride: conflict-free LDS.128
#define KD   3             // K-phase pipeline depth
#define KNT  (D / KET)     // 32 tiles
#define PF   8             // V-phase rolling register prefetch depth

#define SM_KS   (KD * KCH * KSTR)      // 13824 floats
#define SM_QWS  (KD * H * KET)         // 1536 floats
#define SM_AS   (KCH * 20)             // 2560 floats (attn weights [k][h])
#define SMEM_BYTES ((SM_KS + SM_QWS + SM_AS) * 4)   // 71680 B -> 2 blocks/SM

// Scratch (device globals; no allocation allowed)
__device__ float g_qw[Bn * H * D];                    // folded query (q @ wk^T)
__device__ float g_avpart[(size_t)Bn * NC * H * D];   // unnormalized chunk partials
__device__ float g_ms[Bn * NC * H];                   // per-chunk local max
__device__ float g_ss[Bn * NC * H];                   // per-chunk local expsum
__device__ float g_ctx[Bn * D];                       // context after fold

// ---------------------------------------------------------------------------
// cp.async helpers
// ---------------------------------------------------------------------------
__device__ __forceinline__ void cp16(void* s, const void* g) {
    unsigned a = (unsigned)__cvta_generic_to_shared(s);
    asm volatile("cp.async.cg.shared.global [%0], [%1], 16;" :: "r"(a), "l"(g));
}
__device__ __forceinline__ void cp_commit() { asm volatile("cp.async.commit_group;"); }
template<int N> __device__ __forceinline__ void cp_wait() {
    asm volatile("cp.async.wait_group %0;" :: "n"(N));
}

// ---------------------------------------------------------------------------
// Kernel 1: q projection folded through wk. grid (H, B), 256 threads.
// ---------------------------------------------------------------------------
__global__ void __launch_bounds__(256) k_qproj(const float* __restrict__ query,
                                               const float* __restrict__ w_in,
                                               const float* __restrict__ b_in) {
    __shared__ float qs[D];
    __shared__ float qh[HD];
    const int h = blockIdx.x, b = blockIdx.y, tid = threadIdx.x;

    for (int i = tid; i < D; i += 256) qs[i] = query[b * D + i];
    __syncthreads();

    {
        int d = tid >> 2, sub = tid & 3;
        const float* wrow = w_in + (size_t)(h * HD + d) * D;
        float a = 0.f;
        #pragma unroll 8
        for (int e = sub; e < D; e += 4) a = fmaf(qs[e], wrow[e], a);
        a += __shfl_down_sync(0xffffffffu, a, 2, 4);
        a += __shfl_down_sync(0xffffffffu, a, 1, 4);
        if (sub == 0) qh[d] = (a + b_in[h * HD + d]) * 0.125f;
    }
    __syncthreads();

    for (int e = tid; e < D; e += 256) {
        float a = 0.f;
        #pragma unroll
        for (int d = 0; d < HD; d++)
            a = fmaf(qh[d], w_in[(size_t)(D + h * HD + d) * D + e], a);
        g_qw[(b * H + h) * D + e] = a;
    }
}

// ---------------------------------------------------------------------------
// Kernel 2: fused streaming pass (split-KV flash decode) — R16 WIN, unchanged.
// grid (NC, B), 256 threads, 2 blocks/SM.
// ---------------------------------------------------------------------------
__global__ void __launch_bounds__(256, 2) k_stream(const float* __restrict__ past_key,
                                                   const float* __restrict__ key,
                                                   const float* __restrict__ past_value,
                                                   const float* __restrict__ value,
                                                   float* __restrict__ comb_key,
                                                   float* __restrict__ comb_value) {
    extern __shared__ float sm[];
    float (*ks)[KCH][KSTR] = reinterpret_cast<float (*)[KCH][KSTR]>(sm);
    float (*qws)[H][KET]   = reinterpret_cast<float (*)[H][KET]>(sm + SM_KS);
    float (*as)[20]        = reinterpret_cast<float (*)[20]>(sm + SM_KS + SM_QWS);
    __shared__ float red[H][17];
    __shared__ float bcM[H];

    const int chunk = blockIdx.x, b = blockIdx.y, tid = threadIdx.x;
    const int k0 = chunk * KCH;

    // ============================ K PHASE ============================
    {
        const int w = tid >> 5, lane = tid & 31;
        const int hq = w & 3, kh = w >> 2;
        const int pr = tid >> 3, pc = (tid & 7) * 4;

        const float* srcs[4];
        #pragma unroll
        for (int m = 0; m < 4; m++) {
            int kp = k0 + pr + 32 * m;
            srcs[m] = (kp < S) ? past_key + ((size_t)b * S + kp) * D + pc
                               : key + (size_t)b * D + pc;
        }
        const float* qsrc = g_qw + ((size_t)(b * H) + (tid >> 3)) * D + pc;

        #define KPREFETCH(T, BUF)                                           \
            do {                                                            \
                const int _et = (T) * KET;                                  \
                _Pragma("unroll")                                           \
                for (int m = 0; m < 4; m++)                                 \
                    cp16(&ks[BUF][pr + 32 * m][pc], srcs[m] + _et);         \
                if (tid < 128) cp16(&qws[BUF][tid >> 3][pc], qsrc + _et);   \
            } while (0)

        KPREFETCH(0, 0); cp_commit();
        KPREFETCH(1, 1); cp_commit();

        float acc[4][2];
        #pragma unroll
        for (int a = 0; a < 4; a++) { acc[a][0] = 0.f; acc[a][1] = 0.f; }

        const int r0 = lane + 64 * kh;

        for (int t = 0; t < KNT; t++) {
            cp_wait<KD - 2>();
            __syncthreads();
            if (t + KD - 1 < KNT) KPREFETCH(t + KD - 1, (t + KD - 1) % KD);
            cp_commit();

            const int buf = t % KD;
            const int et = t * KET;

            #pragma unroll
            for (int m = 0; m < 4; m++) {
                int kp = k0 + pr + 32 * m;
                if (kp < SP)
                    *(float4*)(comb_key + ((size_t)b * SP + kp) * D + et + pc)
                        = *(const float4*)&ks[buf][pr + 32 * m][pc];
            }
            #pragma unroll
            for (int e4 = 0; e4 < KET / 4; e4++) {
                float4 kv0 = *(const float4*)&ks[buf][r0][e4 * 4];
                float4 kv1 = *(const float4*)&ks[buf][r0 + 32][e4 * 4];
                #pragma unroll
                for (int hh = 0; hh < 4; hh++) {
                    float4 q4 = *(const float4*)&qws[buf][4 * hq + hh][e4 * 4];
                    acc[hh][0] = fmaf(q4.x, kv0.x, acc[hh][0]);
                    acc[hh][0] = fmaf(q4.y, kv0.y, acc[hh][0]);
                    acc[hh][0] = fmaf(q4.z, kv0.z, acc[hh][0]);
                    acc[hh][0] = fmaf(q4.w, kv0.w, acc[hh][0]);
                    acc[hh][1] = fmaf(q4.x, kv1.x, acc[hh][1]);
                    acc[hh][1] = fmaf(q4.y, kv1.y, acc[hh][1]);
                    acc[hh][1] = fmaf(q4.z, kv1.z, acc[hh][1]);
                    acc[hh][1] = fmaf(q4.w, kv1.w, acc[hh][1]);
                }
            }
        }
        #undef KPREFETCH

        __syncthreads();
        #pragma unroll
        for (int hh = 0; hh < 4; hh++)
            #pragma unroll
            for (int jj = 0; jj < 2; jj++) {
                int r = r0 + 32 * jj;
                as[r][4 * hq + hh] = (k0 + r < SP) ? acc[hh][jj] : -1e30f;
            }
    }
    __syncthreads();

    // ======================== LOCAL SOFTMAX ==========================
    {
        const int h = tid & 15, seg = tid >> 4;
        float mloc = -1e30f;
        #pragma unroll
        for (int i = 0; i < 8; i++) mloc = fmaxf(mloc, as[seg * 8 + i][h]);
        red[h][seg] = mloc;
        __syncthreads();
        if (tid < H) {
            float m = red[tid][0];
            #pragma unroll
            for (int s2 = 1; s2 < 16; s2++) m = fmaxf(m, red[tid][s2]);
            bcM[tid] = m;
        }
        __syncthreads();
        const float M = bcM[h];
        float sloc = 0.f;
        #pragma unroll
        for (int i = 0; i < 8; i++) {
            float e = __expf(as[seg * 8 + i][h] - M);
            as[seg * 8 + i][h] = e;
            sloc += e;
        }
        red[h][seg] = sloc;
        __syncthreads();
        if (tid < H) {
            float s2 = 0.f;
            #pragma unroll
            for (int q = 0; q < 16; q++) s2 += red[tid][q];
            g_ms[(b * NC + chunk) * H + tid] = bcM[tid];
            g_ss[(b * NC + chunk) * H + tid] = s2;
        }
    }
    __syncthreads();

    // ============================ V PHASE ============================
    {
        const float* vrow_cur = value + (size_t)b * D + tid * 4;
        const float* pv_base  = past_value + ((size_t)b * S) * D + tid * 4;

        float4 acc[16];
        #pragma unroll
        for (int h = 0; h < 16; h++) acc[h] = make_float4(0.f, 0.f, 0.f, 0.f);

        float4 vbuf[PF];
        #pragma unroll
        for (int p = 0; p < PF; p++) {
            int kp = k0 + p;
            vbuf[p] = *(const float4*)((kp < S) ? pv_base + (size_t)kp * D : vrow_cur);
        }

        for (int kb = 0; kb < KCH; kb += PF) {
            #pragma unroll
            for (int p = 0; p < PF; p++) {
                const int k = kb + p;
                const float4 v = vbuf[p];

                if (kb + PF < KCH) {
                    int kn = k0 + k + PF;
                    vbuf[p] = *(const float4*)((kn < S) ? pv_base + (size_t)kn * D : vrow_cur);
                }
                int kp = k0 + k;
                if (kp < SP)
                    *(float4*)(comb_value + ((size_t)b * SP + kp) * D + tid * 4) = v;

                #pragma unroll
                for (int h4 = 0; h4 < 4; h4++) {
                    float4 w = *(const float4*)&as[k][h4 * 4];
                    acc[h4 * 4 + 0].x = fmaf(w.x, v.x, acc[h4 * 4 + 0].x);
                    acc[h4 * 4 + 0].y = fmaf(w.x, v.y, acc[h4 * 4 + 0].y);
                    acc[h4 * 4 + 0].z = fmaf(w.x, v.z, acc[h4 * 4 + 0].z);
                    acc[h4 * 4 + 0].w = fmaf(w.x, v.w, acc[h4 * 4 + 0].w);
                    acc[h4 * 4 + 1].x = fmaf(w.y, v.x, acc[h4 * 4 + 1].x);
                    acc[h4 * 4 + 1].y = fmaf(w.y, v.y, acc[h4 * 4 + 1].y);
                    acc[h4 * 4 + 1].z = fmaf(w.y, v.z, acc[h4 * 4 + 1].z);
                    acc[h4 * 4 + 1].w = fmaf(w.y, v.w, acc[h4 * 4 + 1].w);
                    acc[h4 * 4 + 2].x = fmaf(w.z, v.x, acc[h4 * 4 + 2].x);
                    acc[h4 * 4 + 2].y = fmaf(w.z, v.y, acc[h4 * 4 + 2].y);
                    acc[h4 * 4 + 2].z = fmaf(w.z, v.z, acc[h4 * 4 + 2].z);
                    acc[h4 * 4 + 2].w = fmaf(w.z, v.w, acc[h4 * 4 + 2].w);
                    acc[h4 * 4 + 3].x = fmaf(w.w, v.x, acc[h4 * 4 + 3].x);
                    acc[h4 * 4 + 3].y = fmaf(w.w, v.y, acc[h4 * 4 + 3].y);
                    acc[h4 * 4 + 3].z = fmaf(w.w, v.z, acc[h4 * 4 + 3].z);
                    acc[h4 * 4 + 3].w = fmaf(w.w, v.w, acc[h4 * 4 + 3].w);
                }
            }
        }

        #pragma unroll
        for (int h = 0; h < 16; h++)
            *(float4*)&g_avpart[(((size_t)b * NC + chunk) * H + h) * D + tid * 4] = acc[h];
    }
}

// ---------------------------------------------------------------------------
// Kernel 3: fold chunk partials with flash rescaling + ctx = av @ wv^T + bv.
// grid (H, B), 256 threads. float4 phase-1 (MLP=33), float4 GEMV phase-2.
// ---------------------------------------------------------------------------
__global__ void __launch_bounds__(256) k_fold(const float* __restrict__ w_in,
                                              const float* __restrict__ b_in) {
    __shared__ float avs[D];
    __shared__ float wch[NC];
    __shared__ float sinv;
    const int h = blockIdx.x, b = blockIdx.y, tid = threadIdx.x;

    if (tid == 0) {
        float M = -1e30f;
        for (int c = 0; c < NC; c++)
            M = fmaxf(M, g_ms[(b * NC + c) * H + h]);
        float Ssum = 0.f;
        for (int c = 0; c < NC; c++) {
            float w = __expf(g_ms[(b * NC + c) * H + h] - M);
            wch[c] = w;
            Ssum += w * g_ss[(b * NC + c) * H + h];
        }
        sinv = 1.f / Ssum;
    }
    __syncthreads();

    // phase 1: combine 33 chunk partials — one float4 per thread, MLP=33
    {
        const float* base = g_avpart + ((size_t)b * NC * H + h) * D + tid * 4;
        float4 s = make_float4(0.f, 0.f, 0.f, 0.f);
        #pragma unroll
        for (int c = 0; c < NC; c++) {
            float4 v = *(const float4*)(base + (size_t)c * H * D);
            float w = wch[c];
            s.x = fmaf(w, v.x, s.x);
            s.y = fmaf(w, v.y, s.y);
            s.z = fmaf(w, v.z, s.z);
            s.w = fmaf(w, v.w, s.w);
        }
        *(float4*)&avs[tid * 4] = s;
    }
    __syncthreads();

    // phase 2: ctx[h*64+d] = avs · wv_row, quad-split float4
    int d = tid >> 2, sub = tid & 3;
    const float* wrow = w_in + (size_t)(2 * D + h * HD + d) * D;
    float4 a4 = make_float4(0.f, 0.f, 0.f, 0.f);
    #pragma unroll 4
    for (int e = sub * 4; e < D; e += 16) {
        float4 w = *(const float4*)(wrow + e);
        float4 v = *(const float4*)&avs[e];
        a4.x = fmaf(w.x, v.x, a4.x);
        a4.y = fmaf(w.y, v.y, a4.y);
        a4.z = fmaf(w.z, v.z, a4.z);
        a4.w = fmaf(w.w, v.w, a4.w);
    }
    float a = (a4.x + a4.y) + (a4.z + a4.w);
    a += __shfl_down_sync(0xffffffffu, a, 2, 4);
    a += __shfl_down_sync(0xffffffffu, a, 1, 4);
    if (sub == 0) g_ctx[b * D + h * HD + d] = a * sinv + b_in[2 * D + h * HD + d];
}

// ---------------------------------------------------------------------------
// Kernel 4: out = ctx @ w_out^T + b_out.
// grid (16 o-groups, 4 batch-groups), 256 thr. Thread: one output o, 4 batches
// (ILP=4); quad-split float4 reads of w_out row (coalesced), ctx in smem.
// ---------------------------------------------------------------------------
__global__ void __launch_bounds__(256) k_out(const float* __restrict__ w_out,
                                             const float* __restrict__ b_out,
                                             float* __restrict__ out) {
    __shared__ float cs[4][D];
    const int og = blockIdx.x, bg = blockIdx.y, tid = threadIdx.x;

    #pragma unroll
    for (int i = tid; i < 4 * D / 4; i += 256) {
        int bb = i >> 8, e4 = i & 255;
        *(float4*)&cs[bb][e4 * 4] =
            *(const float4*)&g_ctx[(bg * 4 + bb) * D + e4 * 4];
    }
    __syncthreads();

    const int d = tid >> 2, sub = tid & 3;
    const int o = og * 64 + d;
    const float* wrow = w_out + (size_t)o * D;

    float4 a0 = make_float4(0.f, 0.f, 0.f, 0.f);
    float4 a1 = make_float4(0.f, 0.f, 0.f, 0.f);
    float4 a2 = make_float4(0.f, 0.f, 0.f, 0.f);
    float4 a3 = make_float4(0.f, 0.f, 0.f, 0.f);
    #pragma unroll 4
    for (int e = sub * 4; e < D; e += 16) {
        float4 w = *(const float4*)(wrow + e);
        float4 v0 = *(const float4*)&cs[0][e];
        float4 v1 = *(const float4*)&cs[1][e];
        float4 v2 = *(const float4*)&cs[2][e];
        float4 v3 = *(const float4*)&cs[3][e];
        a0.x = fmaf(w.x, v0.x, a0.x); a0.y = fmaf(w.y, v0.y, a0.y);
        a0.z = fmaf(w.z, v0.z, a0.z); a0.w = fmaf(w.w, v0.w, a0.w);
        a1.x = fmaf(w.x, v1.x, a1.x); a1.y = fmaf(w.y, v1.y, a1.y);
        a1.z = fmaf(w.z, v1.z, a1.z); a1.w = fmaf(w.w, v1.w, a1.w);
        a2.x = fmaf(w.x, v2.x, a2.x); a2.y = fmaf(w.y, v2.y, a2.y);
        a2.z = fmaf(w.z, v2.z, a2.z); a2.w = fmaf(w.w, v2.w, a2.w);
        a3.x = fmaf(w.x, v3.x, a3.x); a3.y = fmaf(w.y, v3.y, a3.y);
        a3.z = fmaf(w.z, v3.z, a3.z); a3.w = fmaf(w.w, v3.w, a3.w);
    }
    float r0 = (a0.x + a0.y) + (a0.z + a0.w);
    float r1 = (a1.x + a1.y) + (a1.z + a1.w);
    float r2 = (a2.x + a2.y) + (a2.z + a2.w);
    float r3 = (a3.x + a3.y) + (a3.z + a3.w);
    r0 += __shfl_down_sync(0xffffffffu, r0, 2, 4);
    r0 += __shfl_down_sync(0xffffffffu, r0, 1, 4);
    r1 += __shfl_down_sync(0xffffffffu, r1, 2, 4);
    r1 += __shfl_down_sync(0xffffffffu, r1, 1, 4);
    r2 += __shfl_down_sync(0xffffffffu, r2, 2, 4);
    r2 += __shfl_down_sync(0xffffffffu, r2, 1, 4);
    r3 += __shfl_down_sync(0xffffffffu, r3, 2, 4);
    r3 += __shfl_down_sync(0xffffffffu, r3, 1, 4);
    if (sub == 0) {
        float bo = b_out[o];
        out[(size_t)(bg * 4 + 0) * D + o] = r0 + bo;
        out[(size_t)(bg * 4 + 1) * D + o] = r1 + bo;
        out[(size_t)(bg * 4 + 2) * D + o] = r2 + bo;
        out[(size_t)(bg * 4 + 3) * D + o] = r3 + bo;
    }
}

// ---------------------------------------------------------------------------
extern "C" void kernel_launch(void* const* d_in, const int* in_sizes, int n_in,
                              void* d_out, int out_size) {
    (void)in_sizes; (void)n_in; (void)out_size;
    const float* query      = (const float*)d_in[0];
    const float* key        = (const float*)d_in[1];
    const float* value      = (const float*)d_in[2];
    const float* past_key   = (const float*)d_in[3];
    const float* past_value = (const float*)d_in[4];
    const float* w_in       = (const float*)d_in[5];
    const float* b_in       = (const float*)d_in[6];
    const float* w_out      = (const float*)d_in[7];
    const float* b_out      = (const float*)d_in[8];

    float* out        = (float*)d_out;                      // [16,1,1024]
    float* comb_key   = out + (size_t)Bn * D;               // [16,4097,1024]
    float* comb_value = comb_key + (size_t)Bn * SP * D;     // [16,4097,1024]

    cudaFuncSetAttribute(k_stream, cudaFuncAttributeMaxDynamicSharedMemorySize, SMEM_BYTES);

    k_qproj <<<dim3(H, Bn),  256>>>(query, w_in, b_in);
    k_stream<<<dim3(NC, Bn), 256, SMEM_BYTES>>>(past_key, key, past_value, value,
                                                comb_key, comb_value);
    k_fold  <<<dim3(H, Bn),  256>>>(w_in, b_in);
    k_out   <<<dim3(16, 4),  256>>>(w_out, b_out, out);
}